// round 2
// baseline (speedup 1.0000x reference)
#include <cuda_runtime.h>
#include <cstdint>

// Haar DWT2 on x:[8,64,512,512] f32 -> 4 subbands [8,64,256,256] packed
// subband-major into d_out (LL, LH, HL, HH).
//
// Geometry (compile-time constants for this problem):
//   planes P = 8*64 = 512, each 512x512
//   per-plane subband = 256*256 = 65536 elems
//   subband stride in out = P * 65536 = 33,554,432 elems
//
// Each thread: 2 output columns of one output row.
//   reads  float4 from input rows 2i and 2i+1  (32 B)
//   writes float2 to each of 4 subbands        (32 B)

static constexpr int W_IN = 512;
static constexpr int H_OUT = 256;
static constexpr int W_OUT = 256;
static constexpr int PAIRS_PER_ROW = W_OUT / 2;                 // 128 threads per output row
static constexpr long long PLANE_IN = (long long)W_IN * W_IN;   // 262144
static constexpr long long PLANE_OUT = (long long)H_OUT * W_OUT; // 65536
static constexpr long long SUBBAND_STRIDE = 512LL * PLANE_OUT;  // 33,554,432

__global__ void __launch_bounds__(256)
haar_dwt2_kernel(const float* __restrict__ x, float* __restrict__ out)
{
    const unsigned tid = blockIdx.x * blockDim.x + threadIdx.x;
    // tid layout: [plane p : 512][out-row i : 256][col-pair j2 : 128]
    const unsigned j2 = tid & (PAIRS_PER_ROW - 1);       // 0..127
    const unsigned i  = (tid >> 7) & (H_OUT - 1);        // 0..255
    const unsigned p  = tid >> 15;                       // 0..511

    const float* base = x + (long long)p * PLANE_IN + (long long)(2u * i) * W_IN;
    const float4 r0 = __ldg((const float4*)base + j2);              // row 2i,   cols 4*j2..4*j2+3
    const float4 r1 = __ldg((const float4*)base + (W_IN / 4) + j2); // row 2i+1

    // Pixel pair 0: a=r0.x b=r0.y c=r1.x d=r1.y
    // Pixel pair 1: a=r0.z b=r0.w c=r1.z d=r1.w
    const float s = 0.5f;

    float2 ll, lh, hl, hh;
    {
        const float apb = r0.x + r0.y, amb = r0.x - r0.y;
        const float cpd = r1.x + r1.y, cmd = r1.x - r1.y;
        ll.x = (apb + cpd) * s;
        lh.x = (apb - cpd) * s;
        hl.x = (amb + cmd) * s;
        hh.x = (amb - cmd) * s;
    }
    {
        const float apb = r0.z + r0.w, amb = r0.z - r0.w;
        const float cpd = r1.z + r1.w, cmd = r1.z - r1.w;
        ll.y = (apb + cpd) * s;
        lh.y = (apb - cpd) * s;
        hl.y = (amb + cmd) * s;
        hh.y = (amb - cmd) * s;
    }

    const long long obase = (long long)p * PLANE_OUT + (long long)i * W_OUT + 2u * j2;
    float2* o0 = (float2*)(out + obase);
    float2* o1 = (float2*)(out + obase + SUBBAND_STRIDE);
    float2* o2 = (float2*)(out + obase + 2 * SUBBAND_STRIDE);
    float2* o3 = (float2*)(out + obase + 3 * SUBBAND_STRIDE);
    *o0 = ll;
    *o1 = lh;
    *o2 = hl;
    *o3 = hh;
}

extern "C" void kernel_launch(void* const* d_in, const int* in_sizes, int n_in,
                              void* d_out, int out_size)
{
    const float* x = (const float*)d_in[0];
    float* out = (float*)d_out;

    // total threads = 512 planes * 256 rows * 128 pairs = 16,777,216
    const unsigned total = 512u * 256u * 128u;
    const unsigned block = 256u;
    const unsigned grid = total / block; // 65536
    haar_dwt2_kernel<<<grid, block>>>(x, out);
}